// round 14
// baseline (speedup 1.0000x reference)
#include <cuda_runtime.h>
#include <math.h>
#include <stdint.h>

#define BB 8
#define NN 2500
#define EE 100
#define FF 50
#define YY 8922
#define KK 9
#define BY (BB*YY)

#define HS   50        // g_h row stride (stride-50 LDS.64 conflict-free)
#define NTH  640       // 20 warps
#define NGRP 5         // y-groups of 128 threads
#define ATY  20        // NGRP * TR
#define TR   4         // y rows per thread
#define TM   4         // n cols per thread
#define CN   512
#define NCHK 5
#define CHUNK_FLTS (CN*HS)   // 25600

typedef unsigned long long ull;

__device__ float g_h[BB*NN*HS];
__device__ float g_wT[900*52];
__device__ float g_loss[BY];

__device__ __forceinline__ void ffma2(ull &d, ull a, ull b) {
    asm("fma.rn.f32x2 %0, %1, %2, %0;" : "+l"(d) : "l"(a), "l"(b));
}
__device__ __forceinline__ ull pk2(float v) {
    ull r; unsigned u = __float_as_uint(v);
    asm("mov.b64 %0, {%1, %2};" : "=l"(r) : "r"(u), "r"(u));
    return r;
}
__device__ __forceinline__ float lo32(ull v){ return __uint_as_float((unsigned)v); }
__device__ __forceinline__ float hi32(ull v){ return __uint_as_float((unsigned)(v>>32)); }
__device__ __forceinline__ float sum2(ull v){ return lo32(v) + hi32(v); }

__device__ __forceinline__ uint32_t s2u(const void* p) {
    return (uint32_t)__cvta_generic_to_shared(p);
}
__device__ __forceinline__ void mbar_init(uint32_t mbar, int cnt) {
    asm volatile("mbarrier.init.shared.b64 [%0], %1;" :: "r"(mbar), "r"(cnt) : "memory");
}
__device__ __forceinline__ void tma_bulk(uint32_t dst, const void* src, uint32_t bytes, uint32_t mbar) {
    asm volatile("mbarrier.arrive.expect_tx.shared.b64 _, [%0], %1;" :: "r"(mbar), "r"(bytes) : "memory");
    asm volatile("cp.async.bulk.shared::cta.global.mbarrier::complete_tx::bytes [%0], [%1], %2, [%3];"
                 :: "r"(dst), "l"(src), "r"(bytes), "r"(mbar) : "memory");
}
__device__ __forceinline__ void mbar_wait(uint32_t mbar, int parity) {
    uint32_t done;
    do {
        asm volatile("{\n\t.reg .pred p;\n\t"
                     "mbarrier.try_wait.parity.acquire.cta.shared::cta.b64 p, [%1], %2, 0x989680;\n\t"
                     "selp.b32 %0, 1, 0, p;\n\t}"
                     : "=r"(done) : "r"(mbar), "r"((uint32_t)parity) : "memory");
    } while (!done);
}

// ======================= Kernel 0: transpose conv weights (one-shot tiny) =======================
__global__ void wT_kernel(const float* __restrict__ convW) {
    int j = blockIdx.x*1024 + threadIdx.x;
    if (j < FF*EE*KK) {
        int f = j / 900, r = j - f*900;
        g_wT[r*52 + f] = convW[j];
    }
}

// ======================= Kernel 1: embed + conv1d(K=9,SAME) + tanh =======================
#define CVN 96
__global__ __launch_bounds__(384, 1)
void conv_kernel(const int* __restrict__ x, const float* __restrict__ embW,
                 const float* __restrict__ convB) {
    extern __shared__ float sm[];
    ull*   mbar = (ull*)sm;
    float* emb  = sm + 4;               // 104*101
    float* wsm  = emb + 104*101;        // 900*52
    int*   toks = (int*)(wsm + 900*52);

    int b = blockIdx.y, base = blockIdx.x * CVN, tid = threadIdx.x;
    uint32_t mb = s2u(&mbar[0]);

    if (tid < CVN + 8) {
        int n = base - 4 + tid;
        toks[tid] = (n >= 0 && n < NN) ? x[b*NN + n] : -1;
    }
    if (tid == 0) mbar_init(mb, 1);
    __syncthreads();
    if (tid == 0) tma_bulk(s2u(wsm), g_wT, 900*52*4, mb);

    for (int j = tid; j < (CVN+8)*EE; j += 384) {
        int row = j / EE, c = j - row*EE;
        int tk = toks[row];
        emb[row*101 + c] = (tk >= 0) ? embW[(size_t)tk*EE + c] : 0.f;
    }
    __syncthreads();
    mbar_wait(mb, 0);

    int tn = tid % CVN;
    int eq = tid / CVN;

    ull acc[25];
    #pragma unroll
    for (int q = 0; q < 25; q++) acc[q] = 0ull;

    for (int ee = 0; ee < 25; ee++) {
        int e = eq*25 + ee;
        #pragma unroll
        for (int k = 0; k < KK; k++) {
            ull v = pk2(emb[(tn + k)*101 + e]);
            const float* wr = &wsm[(e*KK + k)*52];
            #pragma unroll 4
            for (int i = 0; i < 12; i++) {
                ulonglong2 w2 = *(const ulonglong2*)(wr + 4*i);
                ffma2(acc[2*i],   w2.x, v);
                ffma2(acc[2*i+1], w2.y, v);
            }
            ffma2(acc[24], *(const ull*)(wr + 48), v);
        }
    }
    __syncthreads();
    float* part = sm + 4;
    if (eq > 0) {
        float* p = part + (eq-1)*CVN*FF + tn*FF;
        #pragma unroll
        for (int q = 0; q < 25; q++) {
            p[2*q]   = lo32(acc[q]);
            p[2*q+1] = hi32(acc[q]);
        }
    }
    __syncthreads();
    if (eq == 0) {
        int n = base + tn;
        if (n < NN) {
            float* dst = &g_h[((size_t)b*NN + n)*HS];
            const float* p0 = part + tn*FF;
            const float* p1 = part + CVN*FF + tn*FF;
            const float* p2 = part + 2*CVN*FF + tn*FF;
            #pragma unroll
            for (int q = 0; q < 25; q++) {
                float a0 = lo32(acc[q]) + p0[2*q]   + p1[2*q]   + p2[2*q]   + convB[2*q];
                float a1 = hi32(acc[q]) + p0[2*q+1] + p1[2*q+1] + p2[2*q+1] + convB[2*q+1];
                dst[2*q]   = tanhf(a0);
                dst[2*q+1] = tanhf(a1);
            }
        }
    }
}

// ======================= Kernel 2: fused attention (R6 arch, 20 warps) =======================
// grid (447, 8), 640 threads. tt = tid>>7 (5 y-groups of TR=4), tn = tid&127.
// Pass1: e=exp(U.h)->alpha, d. Pass2: a=e/d, logit += a*(F.h), alpha normalized in place.
__global__ __launch_bounds__(NTH, 1)
void attn_kernel(const float* __restrict__ Uw, const float* __restrict__ finW,
                 const float* __restrict__ finB, const float* __restrict__ tgt,
                 float* __restrict__ yhat_out, float* __restrict__ alpha_out) {
    extern __shared__ float sm[];
    ull*   mbar = (ull*)sm;              // 16B
    float* hbuf = sm + 4;                // 2*CHUNK_FLTS = 51200
    float* Us   = hbuf + 2*CHUNK_FLTS;   // ATY*50 = 1000
    float* Fs   = Us + ATY*FF;           // 1000
    float* red  = Fs + ATY*FF;           // 20 warps * TR = 80
    float* sinv = red + 20*TR;           // 20

    int b = blockIdx.y, y0 = blockIdx.x*ATY, tid = threadIdx.x;
    int tt = tid >> 7, tn = tid & 127;
    int w = tid >> 5, lane = tid & 31;
    const float* hb = g_h + (size_t)b*NN*HS;
    uint32_t mb0 = s2u(&mbar[0]), mb1 = s2u(&mbar[1]);

    if (tid == 0) { mbar_init(mb0, 1); mbar_init(mb1, 1); }
    for (int j = tid; j < ATY*FF; j += NTH) {
        int r = j / FF, f = j - r*FF;
        int yy = y0 + r; if (yy >= YY) yy = YY-1;
        Us[j] = Uw[(size_t)yy*FF + f];
        Fs[j] = finW[(size_t)yy*FF + f];
    }
    __syncthreads();

    int ph0 = 0, ph1 = 0;

    if (tid == 0) tma_bulk(s2u(hbuf), hb, (uint32_t)(CN*HS*4), mb0);

    float d[TR];
    #pragma unroll
    for (int r = 0; r < TR; r++) d[r] = 0.f;

    // ---------------- Pass 1 ----------------
    #pragma unroll 1
    for (int c = 0; c < NCHK; c++) {
        int slot = c & 1;
        if (c + 1 < NCHK && tid == 0) {
            uint32_t bytes = (c + 1 < NCHK - 1) ? (uint32_t)(CN*HS*4)
                                                : (uint32_t)((NN - (NCHK-1)*CN)*HS*4);
            tma_bulk(s2u(hbuf + ((c+1)&1)*CHUNK_FLTS), hb + (size_t)(c+1)*CN*HS, bytes,
                     slot ? mb0 : mb1);
        }
        if (slot == 0) { mbar_wait(mb0, ph0); ph0 ^= 1; }
        else           { mbar_wait(mb1, ph1); ph1 ^= 1; }

        const float* hc = hbuf + slot*CHUNK_FLTS;
        ull acc[TR][TM];
        #pragma unroll
        for (int r = 0; r < TR; r++)
            #pragma unroll
            for (int j = 0; j < TM; j++) acc[r][j] = 0ull;

        #pragma unroll 5
        for (int fp = 0; fp < 25; fp++) {
            ull hv[TM];
            #pragma unroll
            for (int j = 0; j < TM; j++)
                hv[j] = *(const ull*)&hc[(tn + 128*j)*HS + 2*fp];
            ull uv[TR];
            #pragma unroll
            for (int r = 0; r < TR; r++)
                uv[r] = *(const ull*)&Us[(tt*TR + r)*FF + 2*fp];
            #pragma unroll
            for (int r = 0; r < TR; r++)
                #pragma unroll
                for (int j = 0; j < TM; j++) ffma2(acc[r][j], uv[r], hv[j]);
        }

        #pragma unroll
        for (int r = 0; r < TR; r++) {
            int y = y0 + tt*TR + r;
            bool vy = (y < YY);
            float* ao = alpha_out + (size_t)(b*YY + (vy ? y : 0))*NN;
            #pragma unroll
            for (int j = 0; j < TM; j++) {
                int n = c*CN + tn + 128*j;
                if (n < NN) {
                    float e = __expf(sum2(acc[r][j]));
                    d[r] += e;
                    if (vy) ao[n] = e;
                }
            }
        }
        __syncthreads();
    }

    // prefetch pass-2 chunk 0 -> slot NCHK&1 = 1
    if (tid == 0) tma_bulk(s2u(hbuf + (NCHK&1)*CHUNK_FLTS), hb, (uint32_t)(CN*HS*4),
                           (NCHK&1) ? mb1 : mb0);

    // ---- reduce d across the 128 tn-threads (4 warps per y-group) ----
    #pragma unroll
    for (int r = 0; r < TR; r++) {
        float v = d[r];
        #pragma unroll
        for (int o = 16; o; o >>= 1) v += __shfl_xor_sync(~0u, v, o);
        if (lane == 0) red[w*TR + r] = v;
    }
    __syncthreads();
    if (tid < ATY) {
        int g = tid / TR, r = tid - g*TR;
        float s = red[(g*4+0)*TR + r] + red[(g*4+1)*TR + r]
                + red[(g*4+2)*TR + r] + red[(g*4+3)*TR + r];
        sinv[tid] = 1.f / s;
    }
    __syncthreads();

    float inv[TR];
    #pragma unroll
    for (int r = 0; r < TR; r++) inv[r] = sinv[tt*TR + r];

    float lg[TR];
    #pragma unroll
    for (int r = 0; r < TR; r++) lg[r] = 0.f;

    // ---------------- Pass 2 ----------------
    #pragma unroll 1
    for (int c = 0; c < NCHK; c++) {
        int slot = (NCHK + c) & 1;
        if (c + 1 < NCHK && tid == 0) {
            uint32_t bytes = (c + 1 < NCHK - 1) ? (uint32_t)(CN*HS*4)
                                                : (uint32_t)((NN - (NCHK-1)*CN)*HS*4);
            tma_bulk(s2u(hbuf + ((NCHK+c+1)&1)*CHUNK_FLTS), hb + (size_t)(c+1)*CN*HS, bytes,
                     ((NCHK+c+1)&1) ? mb1 : mb0);
        }
        if (slot == 0) { mbar_wait(mb0, ph0); ph0 ^= 1; }
        else           { mbar_wait(mb1, ph1); ph1 ^= 1; }

        const float* hc = hbuf + slot*CHUNK_FLTS;
        ull acc[TR][TM];
        #pragma unroll
        for (int r = 0; r < TR; r++)
            #pragma unroll
            for (int j = 0; j < TM; j++) acc[r][j] = 0ull;

        #pragma unroll 5
        for (int fp = 0; fp < 25; fp++) {
            ull hv[TM];
            #pragma unroll
            for (int j = 0; j < TM; j++)
                hv[j] = *(const ull*)&hc[(tn + 128*j)*HS + 2*fp];
            ull fv[TR];
            #pragma unroll
            for (int r = 0; r < TR; r++)
                fv[r] = *(const ull*)&Fs[(tt*TR + r)*FF + 2*fp];
            #pragma unroll
            for (int r = 0; r < TR; r++)
                #pragma unroll
                for (int j = 0; j < TM; j++) ffma2(acc[r][j], fv[r], hv[j]);
        }

        #pragma unroll
        for (int r = 0; r < TR; r++) {
            int y = y0 + tt*TR + r;
            bool vy = (y < YY);
            float* ao = alpha_out + (size_t)(b*YY + (vy ? y : 0))*NN;
            #pragma unroll
            for (int j = 0; j < TM; j++) {
                int n = c*CN + tn + 128*j;
                if (n < NN && vy) {
                    float a = ao[n] * inv[r];
                    ao[n] = a;
                    lg[r] += a * sum2(acc[r][j]);
                }
            }
        }
        __syncthreads();
    }

    // ---- reduce logits, epilogue ----
    #pragma unroll
    for (int r = 0; r < TR; r++) {
        float v = lg[r];
        #pragma unroll
        for (int o = 16; o; o >>= 1) v += __shfl_xor_sync(~0u, v, o);
        if (lane == 0) red[w*TR + r] = v;
    }
    __syncthreads();
    if (tid < ATY) {
        int g = tid / TR, r = tid - g*TR;
        float v = red[(g*4+0)*TR + r] + red[(g*4+1)*TR + r]
                + red[(g*4+2)*TR + r] + red[(g*4+3)*TR + r];
        int y = y0 + tid;
        if (y < YY) {
            float logit = v + finB[y];
            float p = 1.f / (1.f + __expf(-logit));
            yhat_out[(size_t)b*YY + y] = p;
            float pc = fminf(fmaxf(p, 1e-7f), 1.f - 1e-7f);
            float t = tgt[(size_t)b*YY + y];
            g_loss[(size_t)b*YY + y] = -(t*logf(pc) + (1.f - t)*log1pf(-pc));
        }
    }
}

// ======================= Kernel 3: deterministic loss reduction =======================
__global__ void loss_kernel(float* __restrict__ out) {
    __shared__ float r[1024];
    int tid = threadIdx.x;
    float a = 0.f;
    for (int i = tid; i < BY; i += 1024) a += g_loss[i];
    r[tid] = a;
    __syncthreads();
    for (int st = 512; st > 0; st >>= 1) {
        if (tid < st) r[tid] += r[tid + st];
        __syncthreads();
    }
    if (tid == 0) out[BY] = r[0] / (float)BY;
}

// ======================= Launch =======================
extern "C" void kernel_launch(void* const* d_in, const int* in_sizes, int n_in,
                              void* d_out, int out_size) {
    const int*   x      = (const int*)d_in[0];
    const float* target = (const float*)d_in[1];
    const float* embW   = (const float*)d_in[2];
    const float* convW  = (const float*)d_in[3];
    const float* convB  = (const float*)d_in[4];
    const float* Uw     = (const float*)d_in[5];
    const float* finW   = (const float*)d_in[6];
    const float* finB   = (const float*)d_in[7];
    float* out = (float*)d_out;
    float* yhat  = out;            // [B,Y]
    float* alpha = out + BY + 1;   // [B,Y,N]; out[BY] = loss

    const int conv_smem = (4 + 104*101 + 900*52)*4 + 104*4;             // 229648
    const int attn_smem = (4 + 2*CHUNK_FLTS + 2*ATY*FF + 20*TR + ATY)*4; // ~213 KB

    cudaFuncSetAttribute(conv_kernel, cudaFuncAttributeMaxDynamicSharedMemorySize, conv_smem);
    cudaFuncSetAttribute(attn_kernel, cudaFuncAttributeMaxDynamicSharedMemorySize, attn_smem);

    wT_kernel<<<(FF*EE*KK + 1023)/1024, 1024>>>(convW);
    conv_kernel<<<dim3((NN + CVN - 1)/CVN, BB), 384, conv_smem>>>(x, embW, convB);
    attn_kernel<<<dim3((YY + ATY - 1)/ATY, BB), NTH, attn_smem>>>(Uw, finW, finB, target, yhat, alpha);
    loss_kernel<<<1, 1024>>>(out);
}

// round 15
// speedup vs baseline: 1.0546x; 1.0546x over previous
#include <cuda_runtime.h>
#include <math.h>
#include <stdint.h>

#define BB 8
#define NN 2500
#define EE 100
#define FF 50
#define YY 8922
#define KK 9
#define BY (BB*YY)

#define HS   50        // g_h row stride in floats (stride-50 LDS.64 is bank-conflict-free)
#define ATY  32        // y rows per attn CTA (4 groups x TR)
#define TR   8         // y rows per thread
#define TM   4         // n cols per thread
#define CN   512       // n rows per chunk
#define NCHK 5
#define CHUNK_FLTS (CN*HS)   // 25600

typedef unsigned long long ull;

__device__ float g_h[BB*NN*HS];
__device__ float g_wT[900*52];      // transposed+padded conv weights
__device__ float g_loss[BY];

__device__ __forceinline__ void ffma2(ull &d, ull a, ull b) {
    asm("fma.rn.f32x2 %0, %1, %2, %0;" : "+l"(d) : "l"(a), "l"(b));
}
__device__ __forceinline__ ull pk2(float v) {
    ull r; unsigned u = __float_as_uint(v);
    asm("mov.b64 %0, {%1, %2};" : "=l"(r) : "r"(u), "r"(u));
    return r;
}
__device__ __forceinline__ float lo32(ull v){ return __uint_as_float((unsigned)v); }
__device__ __forceinline__ float hi32(ull v){ return __uint_as_float((unsigned)(v>>32)); }
__device__ __forceinline__ float sum2(ull v){ return lo32(v) + hi32(v); }

__device__ __forceinline__ uint32_t s2u(const void* p) {
    return (uint32_t)__cvta_generic_to_shared(p);
}
__device__ __forceinline__ void mbar_init(uint32_t mbar, int cnt) {
    asm volatile("mbarrier.init.shared.b64 [%0], %1;" :: "r"(mbar), "r"(cnt) : "memory");
}
__device__ __forceinline__ void tma_bulk(uint32_t dst, const void* src, uint32_t bytes, uint32_t mbar) {
    asm volatile("mbarrier.arrive.expect_tx.shared.b64 _, [%0], %1;" :: "r"(mbar), "r"(bytes) : "memory");
    asm volatile("cp.async.bulk.shared::cta.global.mbarrier::complete_tx::bytes [%0], [%1], %2, [%3];"
                 :: "r"(dst), "l"(src), "r"(bytes), "r"(mbar) : "memory");
}
__device__ __forceinline__ void mbar_wait(uint32_t mbar, int parity) {
    uint32_t done;
    do {
        asm volatile("{\n\t.reg .pred p;\n\t"
                     "mbarrier.try_wait.parity.acquire.cta.shared::cta.b64 p, [%1], %2, 0x989680;\n\t"
                     "selp.b32 %0, 1, 0, p;\n\t}"
                     : "=r"(done) : "r"(mbar), "r"((uint32_t)parity) : "memory");
    } while (!done);
}

// ======================= Kernel 0: transpose conv weights (one-shot tiny) =======================
__global__ void wT_kernel(const float* __restrict__ convW) {
    int j = blockIdx.x*1024 + threadIdx.x;      // j = f*900 + r
    if (j < FF*EE*KK) {
        int f = j / 900, r = j - f*900;
        g_wT[r*52 + f] = convW[j];
    }
}

// ======================= Kernel 1: embed + conv1d(K=9,SAME) + tanh =======================
#define CVN 96
__global__ __launch_bounds__(384, 1)
void conv_kernel(const int* __restrict__ x, const float* __restrict__ embW,
                 const float* __restrict__ convB) {
    extern __shared__ float sm[];
    ull*   mbar = (ull*)sm;             // 16B
    float* emb  = sm + 4;               // 104*101 = 10504
    float* wsm  = emb + 104*101;        // 900*52 = 46800
    int*   toks = (int*)(wsm + 900*52); // 104

    int b = blockIdx.y, base = blockIdx.x * CVN, tid = threadIdx.x;
    uint32_t mb = s2u(&mbar[0]);

    if (tid < CVN + 8) {
        int n = base - 4 + tid;
        toks[tid] = (n >= 0 && n < NN) ? x[b*NN + n] : -1;
    }
    if (tid == 0) mbar_init(mb, 1);
    __syncthreads();
    if (tid == 0) tma_bulk(s2u(wsm), g_wT, 900*52*4, mb);

    for (int j = tid; j < (CVN+8)*EE; j += 384) {
        int row = j / EE, c = j - row*EE;
        int tk = toks[row];
        emb[row*101 + c] = (tk >= 0) ? embW[(size_t)tk*EE + c] : 0.f;
    }
    __syncthreads();
    mbar_wait(mb, 0);

    int tn = tid % CVN;
    int eq = tid / CVN;

    ull acc[25];
    #pragma unroll
    for (int q = 0; q < 25; q++) acc[q] = 0ull;

    for (int ee = 0; ee < 25; ee++) {
        int e = eq*25 + ee;
        #pragma unroll
        for (int k = 0; k < KK; k++) {
            ull v = pk2(emb[(tn + k)*101 + e]);
            const float* wr = &wsm[(e*KK + k)*52];
            #pragma unroll 4
            for (int i = 0; i < 12; i++) {
                ulonglong2 w2 = *(const ulonglong2*)(wr + 4*i);
                ffma2(acc[2*i],   w2.x, v);
                ffma2(acc[2*i+1], w2.y, v);
            }
            ffma2(acc[24], *(const ull*)(wr + 48), v);
        }
    }
    __syncthreads();
    float* part = sm + 4;  // aliased scratch 3*96*50 = 14400
    if (eq > 0) {
        float* p = part + (eq-1)*CVN*FF + tn*FF;
        #pragma unroll
        for (int q = 0; q < 25; q++) {
            p[2*q]   = lo32(acc[q]);
            p[2*q+1] = hi32(acc[q]);
        }
    }
    __syncthreads();
    if (eq == 0) {
        int n = base + tn;
        if (n < NN) {
            float* dst = &g_h[((size_t)b*NN + n)*HS];
            const float* p0 = part + tn*FF;
            const float* p1 = part + CVN*FF + tn*FF;
            const float* p2 = part + 2*CVN*FF + tn*FF;
            #pragma unroll
            for (int q = 0; q < 25; q++) {
                float a0 = lo32(acc[q]) + p0[2*q]   + p1[2*q]   + p2[2*q]   + convB[2*q];
                float a1 = hi32(acc[q]) + p0[2*q+1] + p1[2*q+1] + p2[2*q+1] + convB[2*q+1];
                dst[2*q]   = tanhf(a0);
                dst[2*q+1] = tanhf(a1);
            }
        }
    }
}

// ======================= Kernel 2: fused attention (R6 architecture, verbatim) =======================
// grid (279, 8), 512 threads (16 warps). tt = tid>>7 (4 y-groups of TR=8), tn = tid&127.
// Pass1: e=exp(U.h)->alpha, d. Pass2: a=e/d, logit += a*(F.h).
__global__ __launch_bounds__(512, 1)
void attn_kernel(const float* __restrict__ Uw, const float* __restrict__ finW,
                 const float* __restrict__ finB, const float* __restrict__ tgt,
                 float* __restrict__ yhat_out, float* __restrict__ alpha_out) {
    extern __shared__ float sm[];
    ull*   mbar = (ull*)sm;              // 2 mbarriers (16B)
    float* hbuf = sm + 4;                // 2*CHUNK_FLTS = 51200
    float* Us   = hbuf + 2*CHUNK_FLTS;   // ATY*50 = 1600
    float* Fs   = Us + ATY*FF;           // 1600
    float* red  = Fs + ATY*FF;           // 16 warps * TR = 128
    float* sinv = red + 16*TR;           // 32

    int b = blockIdx.y, y0 = blockIdx.x*ATY, tid = threadIdx.x;
    int tt = tid >> 7, tn = tid & 127;
    int w = tid >> 5, lane = tid & 31;
    const float* hb = g_h + (size_t)b*NN*HS;
    uint32_t mb0 = s2u(&mbar[0]), mb1 = s2u(&mbar[1]);

    if (tid == 0) { mbar_init(mb0, 1); mbar_init(mb1, 1); }
    // stage U and F (clamped rows for y >= YY)
    for (int j = tid; j < ATY*FF; j += 512) {
        int r = j / FF, f = j - r*FF;
        int yy = y0 + r; if (yy >= YY) yy = YY-1;
        Us[j] = Uw[(size_t)yy*FF + f];
        Fs[j] = finW[(size_t)yy*FF + f];
    }
    __syncthreads();

    int phase[2] = {0, 0};
    const uint32_t csz[NCHK] = {CN*HS*4, CN*HS*4, CN*HS*4, CN*HS*4, (NN-4*CN)*HS*4};

    // prefetch chunk 0 -> slot 0
    if (tid == 0) tma_bulk(s2u(hbuf), hb, csz[0], mb0);

    float d[TR];
    #pragma unroll
    for (int r = 0; r < TR; r++) d[r] = 0.f;

    // ---------------- Pass 1 ----------------
    for (int c = 0; c < NCHK; c++) {
        int slot = c & 1;
        if (c + 1 < NCHK && tid == 0)
            tma_bulk(s2u(hbuf + ((c+1)&1)*CHUNK_FLTS), hb + (size_t)(c+1)*CN*HS, csz[c+1], slot ? mb0 : mb1);
        mbar_wait(slot ? mb1 : mb0, phase[slot]); phase[slot] ^= 1;

        const float* hc = hbuf + slot*CHUNK_FLTS;
        ull acc[TR][TM];
        #pragma unroll
        for (int r = 0; r < TR; r++)
            #pragma unroll
            for (int j = 0; j < TM; j++) acc[r][j] = 0ull;

        #pragma unroll 5
        for (int fp = 0; fp < 25; fp++) {
            ull hv[TM];
            #pragma unroll
            for (int j = 0; j < TM; j++)
                hv[j] = *(const ull*)&hc[(tn + 128*j)*HS + 2*fp];
            ull uv[TR];
            #pragma unroll
            for (int r = 0; r < TR; r++)
                uv[r] = *(const ull*)&Us[(tt*TR + r)*FF + 2*fp];
            #pragma unroll
            for (int r = 0; r < TR; r++)
                #pragma unroll
                for (int j = 0; j < TM; j++) ffma2(acc[r][j], uv[r], hv[j]);
        }

        #pragma unroll
        for (int r = 0; r < TR; r++) {
            int y = y0 + tt*TR + r;
            bool vy = (y < YY);
            float* ao = alpha_out + (size_t)(b*YY + (vy ? y : 0))*NN;
            #pragma unroll
            for (int j = 0; j < TM; j++) {
                int n = c*CN + tn + 128*j;
                if (n < NN) {
                    float e = __expf(sum2(acc[r][j]));
                    d[r] += e;
                    if (vy) ao[n] = e;
                }
            }
        }
        __syncthreads();
    }

    // prefetch pass-2 chunk 0 -> slot NCHK&1 = 1
    if (tid == 0) tma_bulk(s2u(hbuf + (NCHK&1)*CHUNK_FLTS), hb, csz[0], (NCHK&1) ? mb1 : mb0);

    // ---- reduce d across the 128 tn-threads (4 warps per y-group) ----
    #pragma unroll
    for (int r = 0; r < TR; r++) {
        float v = d[r];
        #pragma unroll
        for (int o = 16; o; o >>= 1) v += __shfl_xor_sync(~0u, v, o);
        if (lane == 0) red[w*TR + r] = v;
    }
    __syncthreads();
    if (tid < ATY) {
        int g = tid / TR, r = tid - g*TR;
        float s = red[(g*4+0)*TR + r] + red[(g*4+1)*TR + r]
                + red[(g*4+2)*TR + r] + red[(g*4+3)*TR + r];
        sinv[tid] = 1.f / s;
    }
    __syncthreads();

    float inv[TR];
    #pragma unroll
    for (int r = 0; r < TR; r++) inv[r] = sinv[tt*TR + r];

    float lg[TR];
    #pragma unroll
    for (int r = 0; r < TR; r++) lg[r] = 0.f;

    // ---------------- Pass 2 ----------------
    for (int c = 0; c < NCHK; c++) {
        int slot = (NCHK + c) & 1;
        if (c + 1 < NCHK && tid == 0)
            tma_bulk(s2u(hbuf + ((NCHK+c+1)&1)*CHUNK_FLTS), hb + (size_t)(c+1)*CN*HS, csz[c+1],
                     ((NCHK+c+1)&1) ? mb1 : mb0);
        mbar_wait(slot ? mb1 : mb0, phase[slot]); phase[slot] ^= 1;

        const float* hc = hbuf + slot*CHUNK_FLTS;
        ull acc[TR][TM];
        #pragma unroll
        for (int r = 0; r < TR; r++)
            #pragma unroll
            for (int j = 0; j < TM; j++) acc[r][j] = 0ull;

        #pragma unroll 5
        for (int fp = 0; fp < 25; fp++) {
            ull hv[TM];
            #pragma unroll
            for (int j = 0; j < TM; j++)
                hv[j] = *(const ull*)&hc[(tn + 128*j)*HS + 2*fp];
            ull fv[TR];
            #pragma unroll
            for (int r = 0; r < TR; r++)
                fv[r] = *(const ull*)&Fs[(tt*TR + r)*FF + 2*fp];
            #pragma unroll
            for (int r = 0; r < TR; r++)
                #pragma unroll
                for (int j = 0; j < TM; j++) ffma2(acc[r][j], fv[r], hv[j]);
        }

        #pragma unroll
        for (int r = 0; r < TR; r++) {
            int y = y0 + tt*TR + r;
            bool vy = (y < YY);
            float* ao = alpha_out + (size_t)(b*YY + (vy ? y : 0))*NN;
            #pragma unroll
            for (int j = 0; j < TM; j++) {
                int n = c*CN + tn + 128*j;
                if (n < NN && vy) {
                    float a = ao[n] * inv[r];
                    ao[n] = a;
                    lg[r] += a * sum2(acc[r][j]);
                }
            }
        }
        __syncthreads();
    }

    // ---- reduce logits, epilogue ----
    #pragma unroll
    for (int r = 0; r < TR; r++) {
        float v = lg[r];
        #pragma unroll
        for (int o = 16; o; o >>= 1) v += __shfl_xor_sync(~0u, v, o);
        if (lane == 0) red[w*TR + r] = v;
    }
    __syncthreads();
    if (tid < ATY) {
        int g = tid / TR, r = tid - g*TR;
        float v = red[(g*4+0)*TR + r] + red[(g*4+1)*TR + r]
                + red[(g*4+2)*TR + r] + red[(g*4+3)*TR + r];
        int y = y0 + tid;
        if (y < YY) {
            float logit = v + finB[y];
            float p = 1.f / (1.f + __expf(-logit));
            yhat_out[(size_t)b*YY + y] = p;
            float pc = fminf(fmaxf(p, 1e-7f), 1.f - 1e-7f);
            float t = tgt[(size_t)b*YY + y];
            g_loss[(size_t)b*YY + y] = -(t*logf(pc) + (1.f - t)*log1pf(-pc));
        }
    }
}

// ======================= Kernel 3: deterministic loss reduction =======================
__global__ void loss_kernel(float* __restrict__ out) {
    __shared__ float r[1024];
    int tid = threadIdx.x;
    float a = 0.f;
    for (int i = tid; i < BY; i += 1024) a += g_loss[i];
    r[tid] = a;
    __syncthreads();
    for (int st = 512; st > 0; st >>= 1) {
        if (tid < st) r[tid] += r[tid + st];
        __syncthreads();
    }
    if (tid == 0) out[BY] = r[0] / (float)BY;
}

// ======================= Launch =======================
extern "C" void kernel_launch(void* const* d_in, const int* in_sizes, int n_in,
                              void* d_out, int out_size) {
    const int*   x      = (const int*)d_in[0];
    const float* target = (const float*)d_in[1];
    const float* embW   = (const float*)d_in[2];
    const float* convW  = (const float*)d_in[3];
    const float* convB  = (const float*)d_in[4];
    const float* Uw     = (const float*)d_in[5];
    const float* finW   = (const float*)d_in[6];
    const float* finB   = (const float*)d_in[7];
    float* out = (float*)d_out;
    float* yhat  = out;            // [B,Y]
    float* alpha = out + BY + 1;   // [B,Y,N]; out[BY] = loss

    const int conv_smem = (4 + 104*101 + 900*52)*4 + 104*4;             // 229648
    const int attn_smem = (4 + 2*CHUNK_FLTS + 2*ATY*FF + 16*TR + 32)*4; // 218272

    cudaFuncSetAttribute(conv_kernel, cudaFuncAttributeMaxDynamicSharedMemorySize, conv_smem);
    cudaFuncSetAttribute(attn_kernel, cudaFuncAttributeMaxDynamicSharedMemorySize, attn_smem);

    wT_kernel<<<(FF*EE*KK + 1023)/1024, 1024>>>(convW);
    conv_kernel<<<dim3((NN + CVN - 1)/CVN, BB), 384, conv_smem>>>(x, embW, convB);
    attn_kernel<<<dim3((YY + ATY - 1)/ATY, BB), 512, attn_smem>>>(Uw, finW, finB, target, yhat, alpha);
    loss_kernel<<<1, 1024>>>(out);
}

// round 16
// speedup vs baseline: 1.5163x; 1.4378x over previous
#include <cuda_runtime.h>
#include <math.h>
#include <stdint.h>

#define BB 8
#define NN 2500
#define EE 100
#define FF 50
#define YY 8922
#define KK 9
#define BY (BB*YY)

#define HS   50        // g_h row stride in floats (stride-50 LDS.64 is bank-conflict-free)
#define ATY  32        // y rows per attn CTA (4 groups x TR)
#define TR   8         // y rows per thread
#define TM   4         // n cols per thread
#define CN   512       // n rows per chunk
#define NCHK 5
#define CHUNK_FLTS (CN*HS)   // 25600

typedef unsigned long long ull;

__device__ float g_h[BB*NN*HS];
__device__ float g_loss[BY];

__device__ __forceinline__ void ffma2(ull &d, ull a, ull b) {
    asm("fma.rn.f32x2 %0, %1, %2, %0;" : "+l"(d) : "l"(a), "l"(b));
}
__device__ __forceinline__ ull pk2(float v) {
    ull r; unsigned u = __float_as_uint(v);
    asm("mov.b64 %0, {%1, %2};" : "=l"(r) : "r"(u), "r"(u));
    return r;
}
__device__ __forceinline__ float lo32(ull v){ return __uint_as_float((unsigned)v); }
__device__ __forceinline__ float hi32(ull v){ return __uint_as_float((unsigned)(v>>32)); }
__device__ __forceinline__ float sum2(ull v){ return lo32(v) + hi32(v); }

__device__ __forceinline__ uint32_t s2u(const void* p) {
    return (uint32_t)__cvta_generic_to_shared(p);
}
__device__ __forceinline__ void mbar_init(uint32_t mbar, int cnt) {
    asm volatile("mbarrier.init.shared.b64 [%0], %1;" :: "r"(mbar), "r"(cnt) : "memory");
}
__device__ __forceinline__ void tma_bulk(uint32_t dst, const void* src, uint32_t bytes, uint32_t mbar) {
    asm volatile("mbarrier.arrive.expect_tx.shared.b64 _, [%0], %1;" :: "r"(mbar), "r"(bytes) : "memory");
    asm volatile("cp.async.bulk.shared::cta.global.mbarrier::complete_tx::bytes [%0], [%1], %2, [%3];"
                 :: "r"(dst), "l"(src), "r"(bytes), "r"(mbar) : "memory");
}
__device__ __forceinline__ void mbar_wait(uint32_t mbar, int parity) {
    uint32_t done;
    do {
        asm volatile("{\n\t.reg .pred p;\n\t"
                     "mbarrier.try_wait.parity.acquire.cta.shared::cta.b64 p, [%1], %2, 0x989680;\n\t"
                     "selp.b32 %0, 1, 0, p;\n\t}"
                     : "=r"(done) : "r"(mbar), "r"((uint32_t)parity) : "memory");
    } while (!done);
}

// ======================= Kernel 1: embed + conv1d(K=9,SAME) + tanh =======================
#define CVN 96
__global__ __launch_bounds__(384, 1)
void conv_kernel(const int* __restrict__ x, const float* __restrict__ embW,
                 const float* __restrict__ convW, const float* __restrict__ convB) {
    extern __shared__ float sm[];
    float* emb = sm;                    // 104*101
    float* wsm = emb + 104*101;         // 900*50
    int*  toks = (int*)(wsm + 45000);

    int b = blockIdx.y, base = blockIdx.x * CVN, tid = threadIdx.x;

    if (tid < CVN + 8) {
        int n = base - 4 + tid;
        toks[tid] = (n >= 0 && n < NN) ? x[b*NN + n] : -1;
    }
    __syncthreads();
    for (int j = tid; j < FF*EE*KK; j += 384) {
        int f = j / 900, r = j - f*900;
        wsm[r*FF + f] = convW[j];
    }
    for (int j = tid; j < (CVN+8)*EE; j += 384) {
        int row = j / EE, c = j - row*EE;
        int tk = toks[row];
        emb[row*101 + c] = (tk >= 0) ? embW[(size_t)tk*EE + c] : 0.f;
    }
    __syncthreads();

    int tn = tid % CVN;
    int eq = tid / CVN;

    ull acc[25];
    #pragma unroll
    for (int q = 0; q < 25; q++) acc[q] = 0ull;

    for (int ee = 0; ee < 25; ee++) {
        int e = eq*25 + ee;
        #pragma unroll
        for (int k = 0; k < KK; k++) {
            ull v = pk2(emb[(tn + k)*101 + e]);
            const ull* wr = (const ull*)&wsm[(e*KK + k)*FF];
            #pragma unroll
            for (int q = 0; q < 25; q++) ffma2(acc[q], wr[q], v);
        }
    }
    __syncthreads();
    float* part = sm;  // aliased scratch 3*96*50
    if (eq > 0) {
        float* p = part + (eq-1)*CVN*FF + tn*FF;
        #pragma unroll
        for (int q = 0; q < 25; q++) {
            p[2*q]   = lo32(acc[q]);
            p[2*q+1] = hi32(acc[q]);
        }
    }
    __syncthreads();
    if (eq == 0) {
        int n = base + tn;
        if (n < NN) {
            float* dst = &g_h[((size_t)b*NN + n)*HS];
            const float* p0 = part + tn*FF;
            const float* p1 = part + CVN*FF + tn*FF;
            const float* p2 = part + 2*CVN*FF + tn*FF;
            #pragma unroll
            for (int q = 0; q < 25; q++) {
                float a0 = lo32(acc[q]) + p0[2*q]   + p1[2*q]   + p2[2*q]   + convB[2*q];
                float a1 = hi32(acc[q]) + p0[2*q+1] + p1[2*q+1] + p2[2*q+1] + convB[2*q+1];
                dst[2*q]   = tanhf(a0);
                dst[2*q+1] = tanhf(a1);
            }
        }
    }
}

// ======================= Kernel 2: fused attention, TMA-staged, reg-tiled =======================
// grid (279, 8), 512 threads (16 warps). tt = tid>>7 (4 y-groups of TR=8), tn = tid&127.
// Pass1: e=exp(U.h)->alpha, d. Pass2: a=e/d, logit += a*(F.h).
__global__ __launch_bounds__(512, 1)
void attn_kernel(const float* __restrict__ Uw, const float* __restrict__ finW,
                 const float* __restrict__ finB, const float* __restrict__ tgt,
                 float* __restrict__ yhat_out, float* __restrict__ alpha_out) {
    extern __shared__ float sm[];
    ull*   mbar = (ull*)sm;              // 2 mbarriers (16B)
    float* hbuf = sm + 4;                // 2*CHUNK_FLTS = 51200
    float* Us   = hbuf + 2*CHUNK_FLTS;   // ATY*50 = 1600
    float* Fs   = Us + ATY*FF;           // 1600
    float* red  = Fs + ATY*FF;           // 16 warps * TR = 128
    float* sinv = red + 16*TR;           // 32

    int b = blockIdx.y, y0 = blockIdx.x*ATY, tid = threadIdx.x;
    int tt = tid >> 7, tn = tid & 127;
    int w = tid >> 5, lane = tid & 31;
    const float* hb = g_h + (size_t)b*NN*HS;
    uint32_t mb0 = s2u(&mbar[0]), mb1 = s2u(&mbar[1]);

    if (tid == 0) { mbar_init(mb0, 1); mbar_init(mb1, 1); }
    // stage U and F (clamped rows for y >= YY)
    for (int j = tid; j < ATY*FF; j += 512) {
        int r = j / FF, f = j - r*FF;
        int yy = y0 + r; if (yy >= YY) yy = YY-1;
        Us[j] = Uw[(size_t)yy*FF + f];
        Fs[j] = finW[(size_t)yy*FF + f];
    }
    __syncthreads();

    int phase[2] = {0, 0};
    const uint32_t csz[NCHK] = {CN*HS*4, CN*HS*4, CN*HS*4, CN*HS*4, (NN-4*CN)*HS*4};

    // prefetch chunk 0 -> slot 0
    if (tid == 0) tma_bulk(s2u(hbuf), hb, csz[0], mb0);

    float d[TR];
    #pragma unroll
    for (int r = 0; r < TR; r++) d[r] = 0.f;

    // ---------------- Pass 1 ----------------
    for (int c = 0; c < NCHK; c++) {
        int slot = c & 1;
        if (c + 1 < NCHK && tid == 0)
            tma_bulk(s2u(hbuf + ((c+1)&1)*CHUNK_FLTS), hb + (size_t)(c+1)*CN*HS, csz[c+1], slot ? mb0 : mb1);
        mbar_wait(slot ? mb1 : mb0, phase[slot]); phase[slot] ^= 1;

        const float* hc = hbuf + slot*CHUNK_FLTS;
        ull acc[TR][TM];
        #pragma unroll
        for (int r = 0; r < TR; r++)
            #pragma unroll
            for (int j = 0; j < TM; j++) acc[r][j] = 0ull;

        #pragma unroll 5
        for (int fp = 0; fp < 25; fp++) {
            ull hv[TM];
            #pragma unroll
            for (int j = 0; j < TM; j++)
                hv[j] = *(const ull*)&hc[(tn + 128*j)*HS + 2*fp];
            ull uv[TR];
            #pragma unroll
            for (int r = 0; r < TR; r++)
                uv[r] = *(const ull*)&Us[(tt*TR + r)*FF + 2*fp];
            #pragma unroll
            for (int r = 0; r < TR; r++)
                #pragma unroll
                for (int j = 0; j < TM; j++) ffma2(acc[r][j], uv[r], hv[j]);
        }

        #pragma unroll
        for (int r = 0; r < TR; r++) {
            int y = y0 + tt*TR + r;
            bool vy = (y < YY);
            float* ao = alpha_out + (size_t)(b*YY + (vy ? y : 0))*NN;
            #pragma unroll
            for (int j = 0; j < TM; j++) {
                int n = c*CN + tn + 128*j;
                if (n < NN) {
                    float e = __expf(sum2(acc[r][j]));
                    d[r] += e;
                    if (vy) ao[n] = e;
                }
            }
        }
        __syncthreads();
    }

    // prefetch pass-2 chunk 0 -> slot NCHK&1 = 1
    if (tid == 0) tma_bulk(s2u(hbuf + (NCHK&1)*CHUNK_FLTS), hb, csz[0], (NCHK&1) ? mb1 : mb0);

    // ---- reduce d across the 128 tn-threads (4 warps per y-group) ----
    #pragma unroll
    for (int r = 0; r < TR; r++) {
        float v = d[r];
        #pragma unroll
        for (int o = 16; o; o >>= 1) v += __shfl_xor_sync(~0u, v, o);
        if (lane == 0) red[w*TR + r] = v;
    }
    __syncthreads();
    if (tid < ATY) {
        int g = tid / TR, r = tid - g*TR;
        float s = red[(g*4+0)*TR + r] + red[(g*4+1)*TR + r]
                + red[(g*4+2)*TR + r] + red[(g*4+3)*TR + r];
        sinv[tid] = 1.f / s;
    }
    __syncthreads();

    float inv[TR];
    #pragma unroll
    for (int r = 0; r < TR; r++) inv[r] = sinv[tt*TR + r];

    float lg[TR];
    #pragma unroll
    for (int r = 0; r < TR; r++) lg[r] = 0.f;

    // ---------------- Pass 2 ----------------
    for (int c = 0; c < NCHK; c++) {
        int slot = (NCHK + c) & 1;
        if (c + 1 < NCHK && tid == 0)
            tma_bulk(s2u(hbuf + ((NCHK+c+1)&1)*CHUNK_FLTS), hb + (size_t)(c+1)*CN*HS, csz[c+1],
                     ((NCHK+c+1)&1) ? mb1 : mb0);
        mbar_wait(slot ? mb1 : mb0, phase[slot]); phase[slot] ^= 1;

        const float* hc = hbuf + slot*CHUNK_FLTS;
        ull acc[TR][TM];
        #pragma unroll
        for (int r = 0; r < TR; r++)
            #pragma unroll
            for (int j = 0; j < TM; j++) acc[r][j] = 0ull;

        #pragma unroll 5
        for (int fp = 0; fp < 25; fp++) {
            ull hv[TM];
            #pragma unroll
            for (int j = 0; j < TM; j++)
                hv[j] = *(const ull*)&hc[(tn + 128*j)*HS + 2*fp];
            ull fv[TR];
            #pragma unroll
            for (int r = 0; r < TR; r++)
                fv[r] = *(const ull*)&Fs[(tt*TR + r)*FF + 2*fp];
            #pragma unroll
            for (int r = 0; r < TR; r++)
                #pragma unroll
                for (int j = 0; j < TM; j++) ffma2(acc[r][j], fv[r], hv[j]);
        }

        #pragma unroll
        for (int r = 0; r < TR; r++) {
            int y = y0 + tt*TR + r;
            bool vy = (y < YY);
            float* ao = alpha_out + (size_t)(b*YY + (vy ? y : 0))*NN;
            #pragma unroll
            for (int j = 0; j < TM; j++) {
                int n = c*CN + tn + 128*j;
                if (n < NN && vy) {
                    float a = ao[n] * inv[r];
                    ao[n] = a;
                    lg[r] += a * sum2(acc[r][j]);
                }
            }
        }
        __syncthreads();
    }

    // ---- reduce logits, epilogue ----
    #pragma unroll
    for (int r = 0; r < TR; r++) {
        float v = lg[r];
        #pragma unroll
        for (int o = 16; o; o >>= 1) v += __shfl_xor_sync(~0u, v, o);
        if (lane == 0) red[w*TR + r] = v;
    }
    __syncthreads();
    if (tid < ATY) {
        int g = tid / TR, r = tid - g*TR;
        float v = red[(g*4+0)*TR + r] + red[(g*4+1)*TR + r]
                + red[(g*4+2)*TR + r] + red[(g*4+3)*TR + r];
        int y = y0 + tid;
        if (y < YY) {
            float logit = v + finB[y];
            float p = 1.f / (1.f + __expf(-logit));
            yhat_out[(size_t)b*YY + y] = p;
            float pc = fminf(fmaxf(p, 1e-7f), 1.f - 1e-7f);
            float t = tgt[(size_t)b*YY + y];
            g_loss[(size_t)b*YY + y] = -(t*logf(pc) + (1.f - t)*log1pf(-pc));
        }
    }
}

// ======================= Kernel 3: deterministic loss reduction =======================
__global__ void loss_kernel(float* __restrict__ out) {
    __shared__ float r[1024];
    int tid = threadIdx.x;
    float a = 0.f;
    for (int i = tid; i < BY; i += 1024) a += g_loss[i];
    r[tid] = a;
    __syncthreads();
    for (int st = 512; st > 0; st >>= 1) {
        if (tid < st) r[tid] += r[tid + st];
        __syncthreads();
    }
    if (tid == 0) out[BY] = r[0] / (float)BY;
}

// ======================= Launch =======================
extern "C" void kernel_launch(void* const* d_in, const int* in_sizes, int n_in,
                              void* d_out, int out_size) {
    const int*   x      = (const int*)d_in[0];
    const float* target = (const float*)d_in[1];
    const float* embW   = (const float*)d_in[2];
    const float* convW  = (const float*)d_in[3];
    const float* convB  = (const float*)d_in[4];
    const float* Uw     = (const float*)d_in[5];
    const float* finW   = (const float*)d_in[6];
    const float* finB   = (const float*)d_in[7];
    float* out = (float*)d_out;
    float* yhat  = out;            // [B,Y]
    float* alpha = out + BY + 1;   // [B,Y,N]; out[BY] = loss

    const int conv_smem = (104*101 + 45000)*4 + 104*4;                      // 222432
    const int attn_smem = (4 + 2*CHUNK_FLTS + 2*ATY*FF + 16*TR + 32)*4;     // 218272

    cudaFuncSetAttribute(conv_kernel, cudaFuncAttributeMaxDynamicSharedMemorySize, conv_smem);
    cudaFuncSetAttribute(attn_kernel, cudaFuncAttributeMaxDynamicSharedMemorySize, attn_smem);

    conv_kernel<<<dim3((NN + CVN - 1)/CVN, BB), 384, conv_smem>>>(x, embW, convW, convB);
    attn_kernel<<<dim3((YY + ATY - 1)/ATY, BB), 512, attn_smem>>>(Uw, finW, finB, target, yhat, alpha);
    loss_kernel<<<1, 1024>>>(out);
}

// round 17
// speedup vs baseline: 1.5585x; 1.0278x over previous
#include <cuda_runtime.h>
#include <math.h>
#include <stdint.h>

#define BB 8
#define NN 2500
#define EE 100
#define FF 50
#define YY 8922
#define KK 9
#define BY (BB*YY)

#define HS   52        // g_h row stride in floats (16B-aligned rows; stride-52 LDS.128 conflict-free)
#define US   52        // U/F smem row stride (16B-aligned)
#define ATY  32        // y rows per attn CTA (4 groups x TR)
#define TR   8         // y rows per thread
#define TM   4         // n cols per thread
#define CN   512       // n rows per chunk
#define NCHK 5
#define CHUNK_FLTS (CN*HS)   // 26624

typedef unsigned long long ull;

__device__ float g_h[BB*NN*HS];
__device__ float g_loss[BY];

__device__ __forceinline__ void ffma2(ull &d, ull a, ull b) {
    asm("fma.rn.f32x2 %0, %1, %2, %0;" : "+l"(d) : "l"(a), "l"(b));
}
__device__ __forceinline__ ull pk2(float v) {
    ull r; unsigned u = __float_as_uint(v);
    asm("mov.b64 %0, {%1, %2};" : "=l"(r) : "r"(u), "r"(u));
    return r;
}
__device__ __forceinline__ float lo32(ull v){ return __uint_as_float((unsigned)v); }
__device__ __forceinline__ float hi32(ull v){ return __uint_as_float((unsigned)(v>>32)); }
__device__ __forceinline__ float sum2(ull v){ return lo32(v) + hi32(v); }

__device__ __forceinline__ uint32_t s2u(const void* p) {
    return (uint32_t)__cvta_generic_to_shared(p);
}
__device__ __forceinline__ void mbar_init(uint32_t mbar, int cnt) {
    asm volatile("mbarrier.init.shared.b64 [%0], %1;" :: "r"(mbar), "r"(cnt) : "memory");
}
__device__ __forceinline__ void tma_bulk(uint32_t dst, const void* src, uint32_t bytes, uint32_t mbar) {
    asm volatile("mbarrier.arrive.expect_tx.shared.b64 _, [%0], %1;" :: "r"(mbar), "r"(bytes) : "memory");
    asm volatile("cp.async.bulk.shared::cta.global.mbarrier::complete_tx::bytes [%0], [%1], %2, [%3];"
                 :: "r"(dst), "l"(src), "r"(bytes), "r"(mbar) : "memory");
}
__device__ __forceinline__ void mbar_wait(uint32_t mbar, int parity) {
    uint32_t done;
    do {
        asm volatile("{\n\t.reg .pred p;\n\t"
                     "mbarrier.try_wait.parity.acquire.cta.shared::cta.b64 p, [%1], %2, 0x989680;\n\t"
                     "selp.b32 %0, 1, 0, p;\n\t}"
                     : "=r"(done) : "r"(mbar), "r"((uint32_t)parity) : "memory");
    } while (!done);
}

// ======================= Kernel 1: embed + conv1d(K=9,SAME) + tanh =======================
#define CVN 96
__global__ __launch_bounds__(384, 1)
void conv_kernel(const int* __restrict__ x, const float* __restrict__ embW,
                 const float* __restrict__ convW, const float* __restrict__ convB) {
    extern __shared__ float sm[];
    float* emb = sm;                    // 104*101
    float* wsm = emb + 104*101;         // 900*50
    int*  toks = (int*)(wsm + 45000);

    int b = blockIdx.y, base = blockIdx.x * CVN, tid = threadIdx.x;

    if (tid < CVN + 8) {
        int n = base - 4 + tid;
        toks[tid] = (n >= 0 && n < NN) ? x[b*NN + n] : -1;
    }
    __syncthreads();
    for (int j = tid; j < FF*EE*KK; j += 384) {
        int f = j / 900, r = j - f*900;
        wsm[r*FF + f] = convW[j];
    }
    for (int j = tid; j < (CVN+8)*EE; j += 384) {
        int row = j / EE, c = j - row*EE;
        int tk = toks[row];
        emb[row*101 + c] = (tk >= 0) ? embW[(size_t)tk*EE + c] : 0.f;
    }
    __syncthreads();

    int tn = tid % CVN;
    int eq = tid / CVN;

    ull acc[25];
    #pragma unroll
    for (int q = 0; q < 25; q++) acc[q] = 0ull;

    for (int ee = 0; ee < 25; ee++) {
        int e = eq*25 + ee;
        #pragma unroll
        for (int k = 0; k < KK; k++) {
            ull v = pk2(emb[(tn + k)*101 + e]);
            const ull* wr = (const ull*)&wsm[(e*KK + k)*FF];
            #pragma unroll
            for (int q = 0; q < 25; q++) ffma2(acc[q], wr[q], v);
        }
    }
    __syncthreads();
    float* part = sm;  // aliased scratch 3*96*50
    if (eq > 0) {
        float* p = part + (eq-1)*CVN*FF + tn*FF;
        #pragma unroll
        for (int q = 0; q < 25; q++) {
            p[2*q]   = lo32(acc[q]);
            p[2*q+1] = hi32(acc[q]);
        }
    }
    __syncthreads();
    if (eq == 0) {
        int n = base + tn;
        if (n < NN) {
            float* dst = &g_h[((size_t)b*NN + n)*HS];
            const float* p0 = part + tn*FF;
            const float* p1 = part + CVN*FF + tn*FF;
            const float* p2 = part + 2*CVN*FF + tn*FF;
            #pragma unroll
            for (int q = 0; q < 25; q++) {
                float a0 = lo32(acc[q]) + p0[2*q]   + p1[2*q]   + p2[2*q]   + convB[2*q];
                float a1 = hi32(acc[q]) + p0[2*q+1] + p1[2*q+1] + p2[2*q+1] + convB[2*q+1];
                dst[2*q]   = tanhf(a0);
                dst[2*q+1] = tanhf(a1);
            }
        }
    }
}

// ======================= Kernel 2: fused attention, TMA-staged, reg-tiled, LDS.128 =======================
// grid (279, 8), 512 threads (16 warps). tt = tid>>7 (4 y-groups of TR=8), tn = tid&127.
// Pass1: e=exp(U.h)->alpha, d. Pass2: a=e/d, logit += a*(F.h).
__global__ __launch_bounds__(512, 1)
void attn_kernel(const float* __restrict__ Uw, const float* __restrict__ finW,
                 const float* __restrict__ finB, const float* __restrict__ tgt,
                 float* __restrict__ yhat_out, float* __restrict__ alpha_out) {
    extern __shared__ float sm[];
    ull*   mbar = (ull*)sm;              // 2 mbarriers (16B)
    float* hbuf = sm + 4;                // 2*CHUNK_FLTS = 53248
    float* Us   = hbuf + 2*CHUNK_FLTS;   // ATY*US = 1664
    float* Fs   = Us + ATY*US;           // 1664
    float* red  = Fs + ATY*US;           // 16 warps * TR = 128
    float* sinv = red + 16*TR;           // 32

    int b = blockIdx.y, y0 = blockIdx.x*ATY, tid = threadIdx.x;
    int tt = tid >> 7, tn = tid & 127;
    int w = tid >> 5, lane = tid & 31;
    const float* hb = g_h + (size_t)b*NN*HS;
    uint32_t mb0 = s2u(&mbar[0]), mb1 = s2u(&mbar[1]);

    if (tid == 0) { mbar_init(mb0, 1); mbar_init(mb1, 1); }
    // stage U and F at stride 52 (clamped rows for y >= YY; pad cols never read)
    for (int j = tid; j < ATY*FF; j += 512) {
        int r = j / FF, f = j - r*FF;
        int yy = y0 + r; if (yy >= YY) yy = YY-1;
        Us[r*US + f] = Uw[(size_t)yy*FF + f];
        Fs[r*US + f] = finW[(size_t)yy*FF + f];
    }
    __syncthreads();

    int phase[2] = {0, 0};
    const uint32_t csz[NCHK] = {CN*HS*4, CN*HS*4, CN*HS*4, CN*HS*4, (NN-4*CN)*HS*4};

    // prefetch chunk 0 -> slot 0
    if (tid == 0) tma_bulk(s2u(hbuf), hb, csz[0], mb0);

    float d[TR];
    #pragma unroll
    for (int r = 0; r < TR; r++) d[r] = 0.f;

    // ---------------- Pass 1 ----------------
    for (int c = 0; c < NCHK; c++) {
        int slot = c & 1;
        if (c + 1 < NCHK && tid == 0)
            tma_bulk(s2u(hbuf + ((c+1)&1)*CHUNK_FLTS), hb + (size_t)(c+1)*CN*HS, csz[c+1], slot ? mb0 : mb1);
        mbar_wait(slot ? mb1 : mb0, phase[slot]); phase[slot] ^= 1;

        const float* hc = hbuf + slot*CHUNK_FLTS;
        ull acc[TR][TM];
        #pragma unroll
        for (int r = 0; r < TR; r++)
            #pragma unroll
            for (int j = 0; j < TM; j++) acc[r][j] = 0ull;

        #pragma unroll 2
        for (int i = 0; i < 12; i++) {
            ulonglong2 hv[TM];
            #pragma unroll
            for (int j = 0; j < TM; j++)
                hv[j] = *(const ulonglong2*)&hc[(tn + 128*j)*HS + 4*i];
            #pragma unroll
            for (int r = 0; r < TR; r++) {
                ulonglong2 uv = *(const ulonglong2*)&Us[(tt*TR + r)*US + 4*i];
                #pragma unroll
                for (int j = 0; j < TM; j++) {
                    ffma2(acc[r][j], uv.x, hv[j].x);
                    ffma2(acc[r][j], uv.y, hv[j].y);
                }
            }
        }
        {   // remainder f = 48,49
            ull hv[TM];
            #pragma unroll
            for (int j = 0; j < TM; j++)
                hv[j] = *(const ull*)&hc[(tn + 128*j)*HS + 48];
            #pragma unroll
            for (int r = 0; r < TR; r++) {
                ull uv = *(const ull*)&Us[(tt*TR + r)*US + 48];
                #pragma unroll
                for (int j = 0; j < TM; j++) ffma2(acc[r][j], uv, hv[j]);
            }
        }

        #pragma unroll
        for (int r = 0; r < TR; r++) {
            int y = y0 + tt*TR + r;
            bool vy = (y < YY);
            float* ao = alpha_out + (size_t)(b*YY + (vy ? y : 0))*NN;
            #pragma unroll
            for (int j = 0; j < TM; j++) {
                int n = c*CN + tn + 128*j;
                if (n < NN) {
                    float e = __expf(sum2(acc[r][j]));
                    d[r] += e;
                    if (vy) ao[n] = e;
                }
            }
        }
        __syncthreads();
    }

    // prefetch pass-2 chunk 0 -> slot NCHK&1 = 1
    if (tid == 0) tma_bulk(s2u(hbuf + (NCHK&1)*CHUNK_FLTS), hb, csz[0], (NCHK&1) ? mb1 : mb0);

    // ---- reduce d across the 128 tn-threads (4 warps per y-group) ----
    #pragma unroll
    for (int r = 0; r < TR; r++) {
        float v = d[r];
        #pragma unroll
        for (int o = 16; o; o >>= 1) v += __shfl_xor_sync(~0u, v, o);
        if (lane == 0) red[w*TR + r] = v;
    }
    __syncthreads();
    if (tid < ATY) {
        int g = tid / TR, r = tid - g*TR;
        float s = red[(g*4+0)*TR + r] + red[(g*4+1)*TR + r]
                + red[(g*4+2)*TR + r] + red[(g*4+3)*TR + r];
        sinv[tid] = 1.f / s;
    }
    __syncthreads();

    float inv[TR];
    #pragma unroll
    for (int r = 0; r < TR; r++) inv[r] = sinv[tt*TR + r];

    float lg[TR];
    #pragma unroll
    for (int r = 0; r < TR; r++) lg[r] = 0.f;

    // ---------------- Pass 2 ----------------
    for (int c = 0; c < NCHK; c++) {
        int slot = (NCHK + c) & 1;
        if (c + 1 < NCHK && tid == 0)
            tma_bulk(s2u(hbuf + ((NCHK+c+1)&1)*CHUNK_FLTS), hb + (size_t)(c+1)*CN*HS, csz[c+1],
                     ((NCHK+c+1)&1) ? mb1 : mb0);
        mbar_wait(slot ? mb1 : mb0, phase[slot]); phase[slot] ^= 1;

        const float* hc = hbuf + slot*CHUNK_FLTS;
        ull acc[TR][TM];
        #pragma unroll
        for (int r = 0; r < TR; r++)
            #pragma unroll
            for (int j = 0; j < TM; j++) acc[r][j] = 0ull;

        #pragma unroll 2
        for (int i = 0; i < 12; i++) {
            ulonglong2 hv[TM];
            #pragma unroll
            for (int j = 0; j < TM; j++)
                hv[j] = *(const ulonglong2*)&hc[(tn + 128*j)*HS + 4*i];
            #pragma unroll
            for (int r = 0; r < TR; r++) {
                ulonglong2 fv = *(const ulonglong2*)&Fs[(tt*TR + r)*US + 4*i];
                #pragma unroll
                for (int j = 0; j < TM; j++) {
                    ffma2(acc[r][j], fv.x, hv[j].x);
                    ffma2(acc[r][j], fv.y, hv[j].y);
                }
            }
        }
        {   // remainder f = 48,49
            ull hv[TM];
            #pragma unroll
            for (int j = 0; j < TM; j++)
                hv[j] = *(const ull*)&hc[(tn + 128*j)*HS + 48];
            #pragma unroll
            for (int r = 0; r < TR; r++) {
                ull fv = *(const ull*)&Fs[(tt*TR + r)*US + 48];
                #pragma unroll
                for (int j = 0; j < TM; j++) ffma2(acc[r][j], fv, hv[j]);
            }
        }

        #pragma unroll
        for (int r = 0; r < TR; r++) {
            int y = y0 + tt*TR + r;
            bool vy = (y < YY);
            float* ao = alpha_out + (size_t)(b*YY + (vy ? y : 0))*NN;
            #pragma unroll
            for (int j = 0; j < TM; j++) {
                int n = c*CN + tn + 128*j;
                if (n < NN && vy) {
                    float a = ao[n] * inv[r];
                    ao[n] = a;
                    lg[r] += a * sum2(acc[r][j]);
                }
            }
        }
        __syncthreads();
    }

    // ---- reduce logits, epilogue ----
    #pragma unroll
    for (int r = 0; r < TR; r++) {
        float v = lg[r];
        #pragma unroll
        for (int o = 16; o; o >>= 1) v += __shfl_xor_sync(~0u, v, o);
        if (lane == 0) red[w*TR + r] = v;
    }
    __syncthreads();
    if (tid < ATY) {
        int g = tid / TR, r = tid - g*TR;
        float v = red[(g*4+0)*TR + r] + red[(g*4+1)*TR + r]
                + red[(g*4+2)*TR + r] + red[(g*4+3)*TR + r];
        int y = y0 + tid;
        if (y < YY) {
            float logit = v + finB[y];
            float p = 1.f / (1.f + __expf(-logit));
            yhat_out[(size_t)b*YY + y] = p;
            float pc = fminf(fmaxf(p, 1e-7f), 1.f - 1e-7f);
            float t = tgt[(size_t)b*YY + y];
            g_loss[(size_t)b*YY + y] = -(t*logf(pc) + (1.f - t)*log1pf(-pc));
        }
    }
}

// ======================= Kernel 3: deterministic loss reduction =======================
__global__ void loss_kernel(float* __restrict__ out) {
    __shared__ float r[1024];
    int tid = threadIdx.x;
    float a = 0.f;
    for (int i = tid; i < BY; i += 1024) a += g_loss[i];
    r[tid] = a;
    __syncthreads();
    for (int st = 512; st > 0; st >>= 1) {
        if (tid < st) r[tid] += r[tid + st];
        __syncthreads();
    }
    if (tid == 0) out[BY] = r[0] / (float)BY;
}

// ======================= Launch =======================
extern "C" void kernel_launch(void* const* d_in, const int* in_sizes, int n_in,
                              void* d_out, int out_size) {
    const int*   x      = (const int*)d_in[0];
    const float* target = (const float*)d_in[1];
    const float* embW   = (const float*)d_in[2];
    const float* convW  = (const float*)d_in[3];
    const float* convB  = (const float*)d_in[4];
    const float* Uw     = (const float*)d_in[5];
    const float* finW   = (const float*)d_in[6];
    const float* finB   = (const float*)d_in[7];
    float* out = (float*)d_out;
    float* yhat  = out;            // [B,Y]
    float* alpha = out + BY + 1;   // [B,Y,N]; out[BY] = loss

    const int conv_smem = (104*101 + 45000)*4 + 104*4;                      // 222432
    const int attn_smem = (4 + 2*CHUNK_FLTS + 2*ATY*US + 16*TR + 32)*4;     // 226960

    cudaFuncSetAttribute(conv_kernel, cudaFuncAttributeMaxDynamicSharedMemorySize, conv_smem);
    cudaFuncSetAttribute(attn_kernel, cudaFuncAttributeMaxDynamicSharedMemorySize, attn_smem);

    conv_kernel<<<dim3((NN + CVN - 1)/CVN, BB), 384, conv_smem>>>(x, embW, convW, convB);
    attn_kernel<<<dim3((YY + ATY - 1)/ATY, BB), 512, attn_smem>>>(Uw, finW, finB, target, yhat, alpha);
    loss_kernel<<<1, 1024>>>(out);
}